// round 6
// baseline (speedup 1.0000x reference)
#include <cuda_runtime.h>
#include <cuda_fp16.h>

#define NN 10000
#define FI 256
#define FO 64
#define BM 128
#define BN 64
#define NSPLIT 7
#define RT 79          // ceil(NN/BM)
#define NT 157         // ceil(NN/BN)
#define ALPHAS 0.2f
#define LOG2E 1.4426950408889634f

// ---------------- device scratch (no allocation allowed) ----------------
__device__ float g_Wh[NN * FO];
__device__ __half g_WhT[(size_t)FO * NN];     // n-major fp16 Wh^T
__device__ float g_f1[NN];                    // pre-scaled by log2e
__device__ float g_f2[NN];                    // pre-scaled by log2e
__device__ float g_pacc[(size_t)NSPLIT * RT * BM * FO];
__device__ float g_pden[NSPLIT * RT * BM];

// ---------------- smem layout (bytes) ----------------
#define PSTB 144                        // 128B data + 16B pad (conflict-free ldmatrix)
#define SM_F2(b)  ((b) * 256)           // 2 x 64 floats
#define SM_DEN    512                   // 128 floats
#define SM_P(b)   (1024 + (b) * 18432)  // 2 x 128*144
#define SM_B(b)   (37888 + (b) * 9216)  // 2 x 64*144
#define SM_TOTAL  56320

// named barrier ids
#define BAR_FULL(b) (1 + (b))
#define BAR_FREE(b) (3 + (b))
#define BAR_PROD    5

// ---------------- PTX helpers ----------------
__device__ __forceinline__ unsigned s2u(const void* p) {
    unsigned a;
    asm("{ .reg .u64 t; cvta.to.shared.u64 t, %1; cvt.u32.u64 %0, t; }"
        : "=r"(a) : "l"(p));
    return a;
}
__device__ __forceinline__ void bar_sync(int id, int cnt) {
    asm volatile("bar.sync %0, %1;" :: "r"(id), "r"(cnt) : "memory");
}
__device__ __forceinline__ void bar_arrive(int id, int cnt) {
    asm volatile("bar.arrive %0, %1;" :: "r"(id), "r"(cnt) : "memory");
}
__device__ __forceinline__ void ldsm4(unsigned* r, unsigned addr) {
    asm volatile("ldmatrix.sync.aligned.m8n8.x4.shared.b16 {%0,%1,%2,%3}, [%4];"
                 : "=r"(r[0]), "=r"(r[1]), "=r"(r[2]), "=r"(r[3]) : "r"(addr));
}
__device__ __forceinline__ void hmma(float* c, const unsigned* a, const unsigned* b) {
    asm volatile(
        "mma.sync.aligned.m16n8k16.row.col.f32.f16.f16.f32 "
        "{%0,%1,%2,%3}, {%4,%5,%6,%7}, {%8,%9}, {%0,%1,%2,%3};"
        : "+f"(c[0]), "+f"(c[1]), "+f"(c[2]), "+f"(c[3])
        : "r"(a[0]), "r"(a[1]), "r"(a[2]), "r"(a[3]), "r"(b[0]), "r"(b[1]));
}
__device__ __forceinline__ float ex2(float x) {
    float r;
    asm("ex2.approx.ftz.f32 %0, %1;" : "=f"(r) : "f"(x));
    return r;
}

// ---------------- Kernel 1: Wh = h @ W  (+ fp16 Wh^T) ----------------
__global__ __launch_bounds__(256) void wh_kernel(const float* __restrict__ h,
                                                 const float* __restrict__ W) {
    __shared__ float sh[16 * FI];
    int row0 = blockIdx.x * 16;
    const float* hp = h + (long long)row0 * FI;
    for (int t = threadIdx.x; t < 16 * FI; t += 256) sh[t] = hp[t];
    __syncthreads();
    int c = threadIdx.x & 63;
    int ty = threadIdx.x >> 6;
    float acc[4] = {0.f, 0.f, 0.f, 0.f};
    for (int k = 0; k < FI; ++k) {
        float w = W[k * FO + c];
        acc[0] += sh[(ty * 4 + 0) * FI + k] * w;
        acc[1] += sh[(ty * 4 + 1) * FI + k] * w;
        acc[2] += sh[(ty * 4 + 2) * FI + k] * w;
        acc[3] += sh[(ty * 4 + 3) * FI + k] * w;
    }
    __half hb[4];
    #pragma unroll
    for (int q = 0; q < 4; ++q) {
        int row = row0 + ty * 4 + q;
        g_Wh[row * FO + c] = acc[q];
        hb[q] = __float2half_rn(acc[q]);
    }
    size_t off = (size_t)c * NN + row0 + ty * 4;
    *(uint2*)&g_WhT[off] = *(uint2*)hb;
}

// ---------------- Kernel 2: f1/f2 (pre-scaled by log2e) ----------------
__global__ __launch_bounds__(128) void f12_kernel(const float* __restrict__ a) {
    int row = blockIdx.x * 4 + (threadIdx.x >> 5);
    int lane = threadIdx.x & 31;
    float w0 = g_Wh[row * FO + lane];
    float w1 = g_Wh[row * FO + 32 + lane];
    float s1 = w0 * a[lane] + w1 * a[lane + 32];
    float s2 = w0 * a[FO + lane] + w1 * a[FO + 32 + lane];
    #pragma unroll
    for (int o = 16; o > 0; o >>= 1) {
        s1 += __shfl_xor_sync(0xffffffffu, s1, o);
        s2 += __shfl_xor_sync(0xffffffffu, s2, o);
    }
    if (lane == 0) { g_f1[row] = s1 * LOG2E; g_f2[row] = s2 * LOG2E; }
}

// ---------------- Kernel 3: warp-specialized P-gen + fp16 MMA -------------
__global__ __launch_bounds__(512, 1) void gat_ws(const int* __restrict__ adj) {
    extern __shared__ char smem[];
    const unsigned sb = s2u(smem);
    float* sden = (float*)(smem + SM_DEN);

    const int tid = threadIdx.x, wid = tid >> 5, lane = tid & 31;
    const int mt = blockIdx.x, jq = blockIdx.y;
    const int i0 = mt * BM;
    const int ntiles = (NT - jq + NSPLIT - 1) / NSPLIT;

    if (wid < 8) {
        // ================= PRODUCER: 8 warps (256 threads) =================
        const int r = tid >> 1, hh = tid & 1;        // row, 32-col half
        const int i = i0 + r;
        const bool rowok = (i < NN);
        const float f1v = rowok ? g_f1[i] : 0.f;
        const int* arow = adj + (size_t)i * NN;
        const int bc = tid >> 2, bseg = tid & 3;     // B staging map

        if (tid < BM) sden[tid] = 0.f;

        int t = jq;
        for (int tt = 0; tt < ntiles; ++tt, t += NSPLIT) {
            const int j0 = t * BN;
            const int b = tt & 1;

            // issue adj LDGs first: latency overlaps the FREE wait below
            const int jb = j0 + hh * 32;
            int4 m[8];
            #pragma unroll
            for (int u = 0; u < 8; ++u) {
                int j = jb + u * 4;
                bool ok = rowok && (j + 3 < NN);
                m[u] = ok ? *(const int4*)(arow + j) : make_int4(0, 0, 0, 0);
            }

            if (tt >= 2) bar_sync(BAR_FREE(b), 512);   // consumers done with buf b

            // stage B tile (WhT fp16, n-major, padded rows)
            #pragma unroll
            for (int ch = 0; ch < 2; ++ch) {
                int e0 = bseg * 16 + ch * 8;
                uint4 v = make_uint4(0, 0, 0, 0);
                if (j0 + e0 + 7 < NN)
                    v = *(const uint4*)(g_WhT + (size_t)bc * NN + j0 + e0);
                *(uint4*)(smem + SM_B(b) + bc * PSTB + e0 * 2) = v;
            }
            // stage f2 slice
            float* sf2 = (float*)(smem + SM_F2(b));
            if (tid < BN) sf2[tid] = (j0 + tid < NN) ? g_f2[j0 + tid] : 0.f;
            bar_sync(BAR_PROD, 256);                   // sf2 (and sden init) visible

            // P-gen (fp16) + denominator from ROUNDED p
            float rsum = 0.f;
            #pragma unroll
            for (int u = 0; u < 8; ++u) {
                float4 f2q = *(const float4*)&sf2[hh * 32 + u * 4];
                float s, p0, p1, p2, p3;
                s = f1v + f2q.x; s = fmaxf(s, ALPHAS * s); p0 = m[u].x ? ex2(s) : 0.f;
                s = f1v + f2q.y; s = fmaxf(s, ALPHAS * s); p1 = m[u].y ? ex2(s) : 0.f;
                s = f1v + f2q.z; s = fmaxf(s, ALPHAS * s); p2 = m[u].z ? ex2(s) : 0.f;
                s = f1v + f2q.w; s = fmaxf(s, ALPHAS * s); p3 = m[u].w ? ex2(s) : 0.f;
                __half2 h01 = __floats2half2_rn(p0, p1);
                __half2 h23 = __floats2half2_rn(p2, p3);
                *(uint2*)(smem + SM_P(b) + r * PSTB + hh * 64 + u * 8) =
                    make_uint2(*(unsigned*)&h01, *(unsigned*)&h23);
                float2 b01 = __half22float2(h01);
                float2 b23 = __half22float2(h23);
                rsum += (b01.x + b01.y) + (b23.x + b23.y);
            }
            rsum += __shfl_down_sync(0xffffffffu, rsum, 1);
            if (!hh) sden[r] += rsum;                  // unique owner per row
            bar_arrive(BAR_FULL(b), 512);              // publish buf b
        }

        bar_sync(BAR_PROD, 256);                       // sden fully visible
        if (tid < BM) g_pden[(jq * RT + mt) * BM + tid] = sden[tid];

    } else {
        // ================= CONSUMER: 8 warps (256 threads) =================
        const int cw = wid - 8;
        const int m0 = cw * 16;
        const unsigned a_off = sb +
            (m0 + (lane & 7) + ((lane >> 3) & 1) * 8) * PSTB + (lane >> 4) * 16;
        const unsigned b_off = sb +
            ((lane & 7) + ((lane >> 4) & 1) * 8) * PSTB + ((lane >> 3) & 1) * 16;

        float acc[8][4];
        #pragma unroll
        for (int nt = 0; nt < 8; ++nt)
            #pragma unroll
            for (int q = 0; q < 4; ++q) acc[nt][q] = 0.f;

        for (int tt = 0; tt < ntiles; ++tt) {
            const int b = tt & 1;
            bar_sync(BAR_FULL(b), 512);                // buf b ready
            const unsigned a_addr = a_off + SM_P(b);
            const unsigned b_addr = b_off + SM_B(b);
            #pragma unroll
            for (int ks = 0; ks < 4; ++ks) {
                unsigned a[4];
                ldsm4(a, a_addr + ks * 32);
                unsigned bfr[16];
                #pragma unroll
                for (int q = 0; q < 4; ++q)
                    ldsm4(bfr + 4 * q, b_addr + q * 16 * PSTB + ks * 32);
                #pragma unroll
                for (int nt = 0; nt < 8; ++nt)
                    hmma(acc[nt], a, bfr + nt * 2);
            }
            bar_arrive(BAR_FREE(b), 512);              // buf b free
        }

        // epilogue: write register partials
        float* pa = g_pacc + (size_t)(jq * RT + mt) * BM * FO;
        int row = m0 + (lane >> 2);
        int col = (lane & 3) * 2;
        #pragma unroll
        for (int nt = 0; nt < 8; ++nt) {
            *(float2*)&pa[row * FO + nt * 8 + col] = make_float2(acc[nt][0], acc[nt][1]);
            *(float2*)&pa[(row + 8) * FO + nt * 8 + col] = make_float2(acc[nt][2], acc[nt][3]);
        }
    }
}

// ---------------- Kernel 4: combine partials + ELU ----------------
__global__ __launch_bounds__(256) void combine_kernel(float* __restrict__ out) {
    int idx = blockIdx.x * 256 + threadIdx.x;
    if (idx >= NN * FO) return;
    int i = idx >> 6, c = idx & 63;
    int mt = i >> 7, row = i & 127;
    float a = 0.f, d = 0.f;
    #pragma unroll
    for (int q = 0; q < NSPLIT; ++q) {
        a += g_pacc[(size_t)(q * RT + mt) * BM * FO + row * FO + c];
        d += g_pden[(q * RT + mt) * BM + row];
    }
    float v = a / d;
    out[idx] = v > 0.f ? v : expm1f(v);
}

extern "C" void kernel_launch(void* const* d_in, const int* in_sizes, int n_in,
                              void* d_out, int out_size) {
    const float* h   = (const float*)d_in[0];
    const int*   adj = (const int*)d_in[1];
    const float* W   = (const float*)d_in[2];
    const float* a   = (const float*)d_in[3];
    float* out = (float*)d_out;

    wh_kernel<<<NN / 16, 256>>>(h, W);
    f12_kernel<<<NN / 4, 128>>>(a);

    cudaFuncSetAttribute(gat_ws, cudaFuncAttributeMaxDynamicSharedMemorySize, SM_TOTAL);
    gat_ws<<<dim3(RT, NSPLIT), 512, SM_TOTAL>>>(adj);

    combine_kernel<<<(NN * FO + 255) / 256, 256>>>(out);
}

// round 7
// speedup vs baseline: 2.3618x; 2.3618x over previous
#include <cuda_runtime.h>
#include <cuda_fp16.h>

#define NN 10000
#define FI 256
#define FO 64
#define BM 128
#define BN 64
#define NSPLIT 7
#define RT 79          // ceil(NN/BM)
#define NT 157         // ceil(NN/BN)
#define ALPHAS 0.2f
#define LOG2E 1.4426950408889634f

// ---------------- device scratch (no allocation allowed) ----------------
__device__ float g_Wh[NN * FO];
__device__ __half g_WhT[(size_t)FO * NN];     // n-major fp16 Wh^T
__device__ float g_f1[NN];                    // pre-scaled by log2e
__device__ float g_f2[NN];                    // pre-scaled by log2e
__device__ float g_pacc[(size_t)NSPLIT * RT * BM * FO];
__device__ float g_pden[NSPLIT * RT * BM];

// ---------------- smem layout (bytes) ----------------
#define PSTB 144                      // 128B data + 16B pad (conflict-free ldmatrix)
#define SM_F1 0                       // 128 floats
#define SM_F2 512                     // 64 floats
#define SM_P  768                     // 128 * 144
#define SM_B  (SM_P + BM * PSTB)      // 19200, 64 * 144
#define SM_TOTAL (SM_B + FO * PSTB)   // 28416 (x2 CTAs = 56KB/SM)

// ---------------- PTX helpers ----------------
__device__ __forceinline__ unsigned s2u(const void* p) {
    unsigned a;
    asm("{ .reg .u64 t; cvta.to.shared.u64 t, %1; cvt.u32.u64 %0, t; }"
        : "=r"(a) : "l"(p));
    return a;
}
__device__ __forceinline__ void ldsm4(unsigned* r, unsigned addr) {
    asm volatile("ldmatrix.sync.aligned.m8n8.x4.shared.b16 {%0,%1,%2,%3}, [%4];"
                 : "=r"(r[0]), "=r"(r[1]), "=r"(r[2]), "=r"(r[3]) : "r"(addr));
}
__device__ __forceinline__ void hmma(float* c, const unsigned* a, const unsigned* b) {
    asm volatile(
        "mma.sync.aligned.m16n8k16.row.col.f32.f16.f16.f32 "
        "{%0,%1,%2,%3}, {%4,%5,%6,%7}, {%8,%9}, {%0,%1,%2,%3};"
        : "+f"(c[0]), "+f"(c[1]), "+f"(c[2]), "+f"(c[3])
        : "r"(a[0]), "r"(a[1]), "r"(a[2]), "r"(a[3]), "r"(b[0]), "r"(b[1]));
}
__device__ __forceinline__ float ex2(float x) {
    float r;
    asm("ex2.approx.ftz.f32 %0, %1;" : "=f"(r) : "f"(x));
    return r;
}

// ---------------- Kernel 1: Wh = h @ W  (+ fp16 Wh^T) ----------------
__global__ __launch_bounds__(256) void wh_kernel(const float* __restrict__ h,
                                                 const float* __restrict__ W) {
    __shared__ float sh[16 * FI];
    int row0 = blockIdx.x * 16;
    const float* hp = h + (long long)row0 * FI;
    for (int t = threadIdx.x; t < 16 * FI; t += 256) sh[t] = hp[t];
    __syncthreads();
    int c = threadIdx.x & 63;
    int ty = threadIdx.x >> 6;
    float acc[4] = {0.f, 0.f, 0.f, 0.f};
    for (int k = 0; k < FI; ++k) {
        float w = W[k * FO + c];
        acc[0] += sh[(ty * 4 + 0) * FI + k] * w;
        acc[1] += sh[(ty * 4 + 1) * FI + k] * w;
        acc[2] += sh[(ty * 4 + 2) * FI + k] * w;
        acc[3] += sh[(ty * 4 + 3) * FI + k] * w;
    }
    __half hb[4];
    #pragma unroll
    for (int q = 0; q < 4; ++q) {
        int row = row0 + ty * 4 + q;
        g_Wh[row * FO + c] = acc[q];
        hb[q] = __float2half_rn(acc[q]);
    }
    size_t off = (size_t)c * NN + row0 + ty * 4;
    *(uint2*)&g_WhT[off] = *(uint2*)hb;
}

// ---------------- Kernel 2: f1/f2 (pre-scaled by log2e) ----------------
__global__ __launch_bounds__(128) void f12_kernel(const float* __restrict__ a) {
    int row = blockIdx.x * 4 + (threadIdx.x >> 5);
    int lane = threadIdx.x & 31;
    float w0 = g_Wh[row * FO + lane];
    float w1 = g_Wh[row * FO + 32 + lane];
    float s1 = w0 * a[lane] + w1 * a[lane + 32];
    float s2 = w0 * a[FO + lane] + w1 * a[FO + 32 + lane];
    #pragma unroll
    for (int o = 16; o > 0; o >>= 1) {
        s1 += __shfl_xor_sync(0xffffffffu, s1, o);
        s2 += __shfl_xor_sync(0xffffffffu, s2, o);
    }
    if (lane == 0) { g_f1[row] = s1 * LOG2E; g_f2[row] = s2 * LOG2E; }
}

// ---------------- Kernel 3: fused P-gen + fp16 MMA (coalesced adj) --------
__global__ __launch_bounds__(256, 2) void gat_mma(const int* __restrict__ adj) {
    extern __shared__ char smem[];
    const unsigned sb = s2u(smem);
    float* sf1 = (float*)(smem + SM_F1);
    float* sf2 = (float*)(smem + SM_F2);

    const int tid = threadIdx.x, wid = tid >> 5, lane = tid & 31;
    const int half = lane >> 4, seg = lane & 15;
    const int mt = blockIdx.x, jq = blockIdx.y;
    const int i0 = mt * BM;
    const int m0 = wid * 16;

    // adj mapping: LDG u -> lanes 0-15 read 256B of row (m0+2u), lanes 16-31 row +1
    const int rbase = i0 + m0 + half;            // + 2u per step
    const int* aptr = adj + (size_t)rbase * NN + seg * 4;

    // B-stage mapping
    const int bc = tid >> 2, bseg = tid & 3;

    // MMA fragment addressing
    const unsigned a_addr = sb + SM_P +
        (m0 + (lane & 7) + ((lane >> 3) & 1) * 8) * PSTB + (lane >> 4) * 16;
    const unsigned b_addr = sb + SM_B +
        ((lane & 7) + ((lane >> 4) & 1) * 8) * PSTB + ((lane >> 3) & 1) * 16;
    // ones-column B fragment (n=0 col of an 8-wide tile): lanes 0-3 hold 1.0
    unsigned bd[2];
    bd[0] = bd[1] = (lane < 4) ? 0x3C003C00u : 0u;

    float acc[8][4], accD[4];
    #pragma unroll
    for (int nt = 0; nt < 8; ++nt)
        #pragma unroll
        for (int q = 0; q < 4; ++q) acc[nt][q] = 0.f;
    #pragma unroll
    for (int q = 0; q < 4; ++q) accD[q] = 0.f;

    if (tid < BM) sf1[tid] = (i0 + tid < NN) ? g_f1[i0 + tid] : 0.f;

    for (int t = jq; t < NT; t += NSPLIT) {
        const int j0 = t * BN;

        // ---- coalesced adj prefetch (4 wavefronts / LDG) ----
        const bool jok = (j0 + seg * 4 + 3) < NN;
        int4 m[8];
        #pragma unroll
        for (int u = 0; u < 8; ++u) {
            bool ok = jok && (rbase + 2 * u < NN);
            m[u] = ok ? *(const int4*)(aptr + (size_t)(2 * u) * NN + j0)
                      : make_int4(0, 0, 0, 0);
        }

        __syncthreads();   // prev MMA done reading sP/sB

        // ---- stage B tile (WhT fp16) + f2 slice ----
        #pragma unroll
        for (int ch = 0; ch < 2; ++ch) {
            int e0 = bseg * 16 + ch * 8;
            uint4 v = make_uint4(0, 0, 0, 0);
            if (j0 + e0 + 7 < NN)
                v = *(const uint4*)(g_WhT + (size_t)bc * NN + j0 + e0);
            *(uint4*)(smem + SM_B + bc * PSTB + e0 * 2) = v;
        }
        if (tid < BN) sf2[tid] = (j0 + tid < NN) ? g_f2[j0 + tid] : 0.f;
        __syncthreads();

        // ---- P-gen: thread handles rows m0+2u+half, cols seg*4..+3 ----
        const float4 f2q = *(const float4*)&sf2[seg * 4];   // loop-invariant
        #pragma unroll
        for (int u = 0; u < 8; ++u) {
            float f1v = sf1[m0 + 2 * u + half];
            float s, p0, p1, p2, p3;
            s = f1v + f2q.x; s = fmaxf(s, ALPHAS * s); p0 = m[u].x ? ex2(s) : 0.f;
            s = f1v + f2q.y; s = fmaxf(s, ALPHAS * s); p1 = m[u].y ? ex2(s) : 0.f;
            s = f1v + f2q.z; s = fmaxf(s, ALPHAS * s); p2 = m[u].z ? ex2(s) : 0.f;
            s = f1v + f2q.w; s = fmaxf(s, ALPHAS * s); p3 = m[u].w ? ex2(s) : 0.f;
            __half2 h01 = __floats2half2_rn(p0, p1);
            __half2 h23 = __floats2half2_rn(p2, p3);
            *(uint2*)(smem + SM_P + (m0 + 2 * u + half) * PSTB + seg * 8) =
                make_uint2(*(unsigned*)&h01, *(unsigned*)&h23);
        }
        __syncthreads();

        // ---- MMA: C += P @ WhT ; denom via ones-column ----
        #pragma unroll
        for (int ks = 0; ks < 4; ++ks) {
            unsigned a[4];
            ldsm4(a, a_addr + ks * 32);
            unsigned bfr[16];
            #pragma unroll
            for (int q = 0; q < 4; ++q)
                ldsm4(bfr + 4 * q, b_addr + q * 16 * PSTB + ks * 32);
            #pragma unroll
            for (int nt = 0; nt < 8; ++nt)
                hmma(acc[nt], a, bfr + nt * 2);
            hmma(accD, a, bd);
        }
    }
    __syncthreads();

    // ---- epilogue ----
    {
        float* pa = g_pacc + (size_t)(jq * RT + mt) * BM * FO;
        int row = m0 + (lane >> 2);
        int col = (lane & 3) * 2;
        #pragma unroll
        for (int nt = 0; nt < 8; ++nt) {
            *(float2*)&pa[row * FO + nt * 8 + col] = make_float2(acc[nt][0], acc[nt][1]);
            *(float2*)&pa[(row + 8) * FO + nt * 8 + col] = make_float2(acc[nt][2], acc[nt][3]);
        }
    }
    if ((lane & 3) == 0) {
        float* pd = g_pden + (jq * RT + mt) * BM;
        int row = m0 + (lane >> 2);
        pd[row] = accD[0];
        pd[row + 8] = accD[2];
    }
}

// ---------------- Kernel 4: combine partials + ELU ----------------
__global__ __launch_bounds__(256) void combine_kernel(float* __restrict__ out) {
    int idx = blockIdx.x * 256 + threadIdx.x;
    if (idx >= NN * FO) return;
    int i = idx >> 6, c = idx & 63;
    int mt = i >> 7, row = i & 127;
    float a = 0.f, d = 0.f;
    #pragma unroll
    for (int q = 0; q < NSPLIT; ++q) {
        a += g_pacc[(size_t)(q * RT + mt) * BM * FO + row * FO + c];
        d += g_pden[(q * RT + mt) * BM + row];
    }
    float v = a / d;
    out[idx] = v > 0.f ? v : expm1f(v);
}

extern "C" void kernel_launch(void* const* d_in, const int* in_sizes, int n_in,
                              void* d_out, int out_size) {
    const float* h   = (const float*)d_in[0];
    const int*   adj = (const int*)d_in[1];
    const float* W   = (const float*)d_in[2];
    const float* a   = (const float*)d_in[3];
    float* out = (float*)d_out;

    wh_kernel<<<NN / 16, 256>>>(h, W);
    f12_kernel<<<NN / 4, 128>>>(a);
    gat_mma<<<dim3(RT, NSPLIT), 256, SM_TOTAL>>>(adj);
    combine_kernel<<<(NN * FO + 255) / 256, 256>>>(out);
}

// round 8
// speedup vs baseline: 2.4077x; 1.0194x over previous
#include <cuda_runtime.h>
#include <cuda_fp16.h>

#define NN 10000
#define FI 256
#define FO 64
#define BM 128
#define BN 64
#define NSPLIT 7
#define RT 79          // ceil(NN/BM)
#define NT 157         // ceil(NN/BN)
#define LOG2E 1.4426950408889634f

// ---------------- device scratch (no allocation allowed) ----------------
__device__ float g_Wh[NN * FO];
__device__ __half g_WhT[(size_t)FO * NN];     // n-major fp16 Wh^T
__device__ float2 g_e1[NN];                   // (exp2(f1'), exp2(0.2 f1'))
__device__ float2 g_e2[NN];                   // (exp2(f2'), exp2(0.2 f2'))
__device__ float g_pacc[(size_t)NSPLIT * RT * BM * FO];
__device__ float g_pden[NSPLIT * RT * BM];

// ---------------- smem layout (bytes) ----------------
#define PSTB 144                      // 128B data + 16B pad (conflict-free ldmatrix)
#define SM_E1 0                       // 128 float2 = 1024B
#define SM_E2 1024                    // 64 float2 = 512B
#define SM_P  1536                    // 128 * 144
#define SM_B  (SM_P + BM * PSTB)      // 64 * 144
#define SM_TOTAL (SM_B + FO * PSTB)   // 29184 (x2 CTAs = 57KB/SM)

// ---------------- PTX helpers ----------------
__device__ __forceinline__ unsigned s2u(const void* p) {
    unsigned a;
    asm("{ .reg .u64 t; cvta.to.shared.u64 t, %1; cvt.u32.u64 %0, t; }"
        : "=r"(a) : "l"(p));
    return a;
}
__device__ __forceinline__ void ldsm4(unsigned* r, unsigned addr) {
    asm volatile("ldmatrix.sync.aligned.m8n8.x4.shared.b16 {%0,%1,%2,%3}, [%4];"
                 : "=r"(r[0]), "=r"(r[1]), "=r"(r[2]), "=r"(r[3]) : "r"(addr));
}
__device__ __forceinline__ void hmma(float* c, const unsigned* a, const unsigned* b) {
    asm volatile(
        "mma.sync.aligned.m16n8k16.row.col.f32.f16.f16.f32 "
        "{%0,%1,%2,%3}, {%4,%5,%6,%7}, {%8,%9}, {%0,%1,%2,%3};"
        : "+f"(c[0]), "+f"(c[1]), "+f"(c[2]), "+f"(c[3])
        : "r"(a[0]), "r"(a[1]), "r"(a[2]), "r"(a[3]), "r"(b[0]), "r"(b[1]));
}

// ---------------- Kernel 1: Wh = h @ W  (+ fp16 Wh^T) ----------------
__global__ __launch_bounds__(256) void wh_kernel(const float* __restrict__ h,
                                                 const float* __restrict__ W) {
    __shared__ float sh[16 * FI];
    int row0 = blockIdx.x * 16;
    const float* hp = h + (long long)row0 * FI;
    for (int t = threadIdx.x; t < 16 * FI; t += 256) sh[t] = hp[t];
    __syncthreads();
    int c = threadIdx.x & 63;
    int ty = threadIdx.x >> 6;
    float acc[4] = {0.f, 0.f, 0.f, 0.f};
    for (int k = 0; k < FI; ++k) {
        float w = W[k * FO + c];
        acc[0] += sh[(ty * 4 + 0) * FI + k] * w;
        acc[1] += sh[(ty * 4 + 1) * FI + k] * w;
        acc[2] += sh[(ty * 4 + 2) * FI + k] * w;
        acc[3] += sh[(ty * 4 + 3) * FI + k] * w;
    }
    __half hb[4];
    #pragma unroll
    for (int q = 0; q < 4; ++q) {
        int row = row0 + ty * 4 + q;
        g_Wh[row * FO + c] = acc[q];
        hb[q] = __float2half_rn(acc[q]);
    }
    size_t off = (size_t)c * NN + row0 + ty * 4;
    *(uint2*)&g_WhT[off] = *(uint2*)hb;
}

// ---------------- Kernel 2: f1/f2 -> exp2 pair tables ----------------
__global__ __launch_bounds__(128) void f12_kernel(const float* __restrict__ a) {
    int row = blockIdx.x * 4 + (threadIdx.x >> 5);
    int lane = threadIdx.x & 31;
    float w0 = g_Wh[row * FO + lane];
    float w1 = g_Wh[row * FO + 32 + lane];
    float s1 = w0 * a[lane] + w1 * a[lane + 32];
    float s2 = w0 * a[FO + lane] + w1 * a[FO + 32 + lane];
    #pragma unroll
    for (int o = 16; o > 0; o >>= 1) {
        s1 += __shfl_xor_sync(0xffffffffu, s1, o);
        s2 += __shfl_xor_sync(0xffffffffu, s2, o);
    }
    if (lane == 0) {
        s1 *= LOG2E; s2 *= LOG2E;
        g_e1[row] = make_float2(exp2f(s1), exp2f(0.2f * s1));
        g_e2[row] = make_float2(exp2f(s2), exp2f(0.2f * s2));
    }
}

// ---------------- Kernel 3: fused P-gen (no exp) + fp16 MMA ---------------
__global__ __launch_bounds__(256, 2) void gat_mma(const int* __restrict__ adj) {
    extern __shared__ char smem[];
    const unsigned sb = s2u(smem);
    float2* se1 = (float2*)(smem + SM_E1);
    float2* se2 = (float2*)(smem + SM_E2);

    const int tid = threadIdx.x, wid = tid >> 5, lane = tid & 31;
    const int half = lane >> 4, seg = lane & 15;
    const int mt = blockIdx.x, jq = blockIdx.y;
    const int i0 = mt * BM;
    const int m0 = wid * 16;

    // adj mapping: LDG u -> lanes 0-15 read 256B of row (m0+2u), lanes 16-31 row +1
    const int rbase = i0 + m0 + half;
    const int* aptr = adj + (size_t)rbase * NN + seg * 4;

    // B-stage mapping
    const int bc = tid >> 2, bseg = tid & 3;

    // MMA fragment addressing
    const unsigned a_addr = sb + SM_P +
        (m0 + (lane & 7) + ((lane >> 3) & 1) * 8) * PSTB + (lane >> 4) * 16;
    const unsigned b_addr = sb + SM_B +
        ((lane & 7) + ((lane >> 4) & 1) * 8) * PSTB + ((lane >> 3) & 1) * 16;
    // ones-column B fragment: lanes 0-3 hold 1.0 in both halves
    unsigned bd[2];
    bd[0] = bd[1] = (lane < 4) ? 0x3C003C00u : 0u;

    float acc[8][4], accD[4];
    #pragma unroll
    for (int nt = 0; nt < 8; ++nt)
        #pragma unroll
        for (int q = 0; q < 4; ++q) acc[nt][q] = 0.f;
    #pragma unroll
    for (int q = 0; q < 4; ++q) accD[q] = 0.f;

    if (tid < BM) {
        int i = i0 + tid;
        se1[tid] = (i < NN) ? g_e1[i] : make_float2(0.f, 0.f);
    }

    for (int t = jq; t < NT; t += NSPLIT) {
        const int j0 = t * BN;

        // ---- coalesced adj prefetch (4 wavefronts / LDG) ----
        const bool jok = (j0 + seg * 4 + 3) < NN;
        int4 m[8];
        #pragma unroll
        for (int u = 0; u < 8; ++u) {
            bool ok = jok && (rbase + 2 * u < NN);
            m[u] = ok ? *(const int4*)(aptr + (size_t)(2 * u) * NN + j0)
                      : make_int4(0, 0, 0, 0);
        }

        __syncthreads();   // prev MMA done reading sP/sB (se1 stable after first)

        // ---- stage B tile (WhT fp16) + e2 slice ----
        #pragma unroll
        for (int ch = 0; ch < 2; ++ch) {
            int e0 = bseg * 16 + ch * 8;
            uint4 v = make_uint4(0, 0, 0, 0);
            if (j0 + e0 + 7 < NN)
                v = *(const uint4*)(g_WhT + (size_t)bc * NN + j0 + e0);
            *(uint4*)(smem + SM_B + bc * PSTB + e0 * 2) = v;
        }
        if (tid < BN) {
            int j = j0 + tid;
            se2[tid] = (j < NN) ? g_e2[j] : make_float2(0.f, 0.f);
        }
        __syncthreads();

        // ---- P-gen: p = m ? max(E1*E2, E1a*E2a) : 0 ----
        float2 e2q[4];
        #pragma unroll
        for (int c = 0; c < 4; ++c) e2q[c] = se2[seg * 4 + c];   // loop-invariant
        #pragma unroll
        for (int u = 0; u < 8; ++u) {
            float2 e1 = se1[m0 + 2 * u + half];
            float p0 = fmaxf(e1.x * e2q[0].x, e1.y * e2q[0].y);
            float p1 = fmaxf(e1.x * e2q[1].x, e1.y * e2q[1].y);
            float p2 = fmaxf(e1.x * e2q[2].x, e1.y * e2q[2].y);
            float p3 = fmaxf(e1.x * e2q[3].x, e1.y * e2q[3].y);
            p0 = m[u].x ? p0 : 0.f;
            p1 = m[u].y ? p1 : 0.f;
            p2 = m[u].z ? p2 : 0.f;
            p3 = m[u].w ? p3 : 0.f;
            __half2 h01 = __floats2half2_rn(p0, p1);
            __half2 h23 = __floats2half2_rn(p2, p3);
            *(uint2*)(smem + SM_P + (m0 + 2 * u + half) * PSTB + seg * 8) =
                make_uint2(*(unsigned*)&h01, *(unsigned*)&h23);
        }
        __syncthreads();

        // ---- MMA: C += P @ WhT ; denom via ones-column ----
        #pragma unroll
        for (int ks = 0; ks < 4; ++ks) {
            unsigned a[4];
            ldsm4(a, a_addr + ks * 32);
            unsigned bfr[16];
            #pragma unroll
            for (int q = 0; q < 4; ++q)
                ldsm4(bfr + 4 * q, b_addr + q * 16 * PSTB + ks * 32);
            #pragma unroll
            for (int nt = 0; nt < 8; ++nt)
                hmma(acc[nt], a, bfr + nt * 2);
            hmma(accD, a, bd);
        }
    }
    __syncthreads();

    // ---- epilogue ----
    {
        float* pa = g_pacc + (size_t)(jq * RT + mt) * BM * FO;
        int row = m0 + (lane >> 2);
        int col = (lane & 3) * 2;
        #pragma unroll
        for (int nt = 0; nt < 8; ++nt) {
            *(float2*)&pa[row * FO + nt * 8 + col] = make_float2(acc[nt][0], acc[nt][1]);
            *(float2*)&pa[(row + 8) * FO + nt * 8 + col] = make_float2(acc[nt][2], acc[nt][3]);
        }
    }
    if ((lane & 3) == 0) {
        float* pd = g_pden + (jq * RT + mt) * BM;
        int row = m0 + (lane >> 2);
        pd[row] = accD[0];
        pd[row + 8] = accD[2];
    }
}

// ---------------- Kernel 4: combine partials + ELU ----------------
__global__ __launch_bounds__(256) void combine_kernel(float* __restrict__ out) {
    int idx = blockIdx.x * 256 + threadIdx.x;
    if (idx >= NN * FO) return;
    int i = idx >> 6, c = idx & 63;
    int mt = i >> 7, row = i & 127;
    float a = 0.f, d = 0.f;
    #pragma unroll
    for (int q = 0; q < NSPLIT; ++q) {
        a += g_pacc[(size_t)(q * RT + mt) * BM * FO + row * FO + c];
        d += g_pden[(q * RT + mt) * BM + row];
    }
    float v = a / d;
    out[idx] = v > 0.f ? v : expm1f(v);
}

extern "C" void kernel_launch(void* const* d_in, const int* in_sizes, int n_in,
                              void* d_out, int out_size) {
    const float* h   = (const float*)d_in[0];
    const int*   adj = (const int*)d_in[1];
    const float* W   = (const float*)d_in[2];
    const float* a   = (const float*)d_in[3];
    float* out = (float*)d_out;

    wh_kernel<<<NN / 16, 256>>>(h, W);
    f12_kernel<<<NN / 4, 128>>>(a);
    gat_mma<<<dim3(RT, NSPLIT), 256, SM_TOTAL>>>(adj);
    combine_kernel<<<(NN * FO + 255) / 256, 256>>>(out);
}